// round 16
// baseline (speedup 1.0000x reference)
#include <cuda_runtime.h>
#include <cuda_bf16.h>
#include <cstdint>

// Problem constants
#define BB 16
#define SS 1024
#define DD 512
#define HH 8
#define DKK 64
#define MROWS (BB*SS)          // 16384
#define ELEMS (MROWS*DD)       // 8388608
#define WSZ (DD*DD)            // 262144

// ---------------- scratch buffers (no allocation allowed) ----------------
__device__ float g_Qh[ELEMS];   // [B,H,S,DK]  (tf32-rounded)
__device__ float g_Kh[ELEMS];
__device__ float g_Vh[ELEMS];
__device__ float g_ctx[ELEMS];  // [B*S, D]
__device__ float g_att[ELEMS];  // ctx @ W_o
__device__ float g_out1[ELEMS]; // after first LN
__device__ float g_hid[ELEMS];  // gelu(out1 @ lin1 + b1) (tf32-rounded)
__device__ float g_ffn[ELEMS];  // hid @ lin2 + b2
__device__ float g_Wr[6 * WSZ]; // tf32-rounded weights, original [k][n] layout

// ---------------- helpers ----------------
__device__ __forceinline__ float gelu_tanh_f(float x) {
    float x3 = x * x * x;
    return 0.5f * x * (1.0f + tanhf(0.7978845608028654f * (x + 0.044715f * x3)));
}

__device__ __forceinline__ uint32_t cvt_tf32(float x) {
    uint32_t u;
    asm("cvt.rna.tf32.f32 %0, %1;" : "=r"(u) : "f"(x));
    return u;
}
__device__ __forceinline__ float rna_tf32f(float x) {
    return __uint_as_float(cvt_tf32(x));
}

__device__ __forceinline__ void mma_tf32(
    float& d0, float& d1, float& d2, float& d3,
    uint32_t a0, uint32_t a1, uint32_t a2, uint32_t a3,
    uint32_t b0, uint32_t b1)
{
    asm volatile(
        "mma.sync.aligned.m16n8k8.row.col.f32.tf32.tf32.f32 "
        "{%0,%1,%2,%3}, {%4,%5,%6,%7}, {%8,%9}, {%0,%1,%2,%3};\n"
        : "+f"(d0), "+f"(d1), "+f"(d2), "+f"(d3)
        : "r"(a0), "r"(a1), "r"(a2), "r"(a3), "r"(b0), "r"(b1));
}

__device__ __forceinline__ uint32_t smem_u32(const void* p) {
    return (uint32_t)__cvta_generic_to_shared(p);
}
#define CP_ASYNC16(dst, src) \
    asm volatile("cp.async.cg.shared.global [%0], [%1], 16;\n" :: "r"(dst), "l"(src))
#define CP_COMMIT() asm volatile("cp.async.commit_group;\n")
#define CP_WAIT1()  asm volatile("cp.async.wait_group 1;\n")
#define CP_WAIT0()  asm volatile("cp.async.wait_group 0;\n")

// ============ weight rna pre-round (layout preserved [k][n]) ==============
__global__ __launch_bounds__(256) void wround_kernel(
    const float* __restrict__ W0, const float* __restrict__ W1,
    const float* __restrict__ W2, const float* __restrict__ W3,
    const float* __restrict__ W4, const float* __restrict__ W5,
    float* __restrict__ out)
{
    const float* Ws[6] = {W0, W1, W2, W3, W4, W5};
    const int z = blockIdx.y;
    const int idx = blockIdx.x * 256 + threadIdx.x;   // float4 index, 65536/matrix
    float4 v = ((const float4*)Ws[z])[idx];
    v.x = rna_tf32f(v.x); v.y = rna_tf32f(v.y);
    v.z = rna_tf32f(v.z); v.w = rna_tf32f(v.w);
    ((float4*)(out + (long)z * WSZ))[idx] = v;
}

// ================= TF32 GEMM 128x128x32, 4 warps x (64x64) warp tile ======
// 128 threads. A staged LDG->rna->STS into FRAGMENT-MAJOR layout:
//   per (k-chunk c, warpM, lane) a block of 4 float4s (padded to 5);
//   float4 #mi = {a0,a1,a2,a3} = A(m,k),(m+8,k),(m,k+4),(m+8,k+4)
//   for m = warpM*64+mi*16+(lane>>2), k = c*8+(lane&3).
//   -> consumer does 4x LDS.128 per k-step (was 16x LDS.32), conflict-free
//   (lane stride 5 f4: banks 4*((5l+mi)%8) distinct per 8-lane phase).
// B: [k][n] pad 136, cp.async, THREE stages, issued 2 iters ahead,
//   one commit group per iter (possibly empty), wait_group<=1 at iter end.
// A: TWO stages (writes are barrier-ordered register stores).
#define TBK 32
#define A2_STAGE 5120        // floats per A stage (256 lane-blocks x 5 f4)
#define B_STAGE (TBK*136)    // 4352 floats
#define GEMM_SMEM_BYTES ((2*A2_STAGE + 3*B_STAGE)*4)   // 93184

enum { EPI_QKV = 0, EPI_PLAIN = 1, EPI_BIAS = 2, EPI_BIASGELU = 3 };

template <int EPI>
__device__ __forceinline__ void gemm_body(
    const float* __restrict__ A,     // [16384, 512] fp32
    const float* __restrict__ Bw,    // [512, 512] fp32, pre-rounded tf32
    const float* __restrict__ bias,  // [512] or null
    float* __restrict__ C, float scale)
{
    extern __shared__ float gsm[];
    float* const Bbase = gsm + 2 * A2_STAGE;

    const int tid  = threadIdx.x;     // 0..127
    const int lane = tid & 31;
    const int warp = tid >> 5;        // 0..3
    const int warpM = warp >> 1;      // 0..1
    const int warpN = warp & 1;       // 0..1
    const int g  = lane >> 2;         // 0..7
    const int tg = lane & 3;          // 0..3

    const int mBase = warpM * 64;
    const int nBase = warpN * 64;

    const long rowBlock = (long)blockIdx.y * 128;
    const int  colBlock = blockIdx.x * 128;

    // loader mapping (1024 float4 per tile, 8 per thread)
    const int lrA = tid >> 3;             // 0..15 -> rows lrA + 16*i
    const int lcA = (tid & 7) << 2;       // 0..28 (4 consecutive k)
    const int lrB = tid >> 5;             // 0..3  -> k-rows lrB + 4*i
    const int lcB = (tid & 31) << 2;      // 0..124

    // A staging decomposition (k side, fixed per thread)
    const int cA  = lcA >> 3;             // k-chunk 0..3
    const int jkA = (lcA >> 2) & 1;       // k-half within chunk

    float acc[4][8][4];
    #pragma unroll
    for (int i = 0; i < 4; i++)
        #pragma unroll
        for (int j = 0; j < 8; j++)
            #pragma unroll
            for (int c = 0; c < 4; c++) acc[i][j][c] = 0.0f;

    const int nt = 512 / TBK;   // 16

    auto issueB = [&](int kt, int stage) {
        float* BsS = Bbase + stage * B_STAGE;
        #pragma unroll
        for (int i = 0; i < 8; i++) {
            int r = lrB + 4 * i;
            CP_ASYNC16(smem_u32(&BsS[r * 136 + lcB]),
                       Bw + (long)(kt + r) * 512 + colBlock + lcB);
        }
    };
    auto ldA = [&](int kt, float4* ar) {
        #pragma unroll
        for (int i = 0; i < 8; i++) {
            int r = lrA + 16 * i;
            ar[i] = *(const float4*)(A + (rowBlock + r) * 512 + kt + lcA);
        }
    };
    // fragment-major scatter store (rna applied here)
    auto stA = [&](int stage, const float4* ar) {
        float* AsS = gsm + stage * A2_STAGE;
        #pragma unroll
        for (int i = 0; i < 8; i++) {
            int r = lrA + 16 * i;
            int wM  = r >> 6;
            int rem = r & 63;
            int mi  = rem >> 4;
            int gg  = rem & 7;
            int jm  = (rem >> 3) & 1;
            const int b = jkA * 2 + jm;
            float vv[4];
            vv[0] = rna_tf32f(ar[i].x); vv[1] = rna_tf32f(ar[i].y);
            vv[2] = rna_tf32f(ar[i].z); vv[3] = rna_tf32f(ar[i].w);
            // element e -> tg=e -> lane2 = gg*4+e
            int base = (((cA * 2 + wM) * 32 + gg * 4) * 5 + mi) * 4 + b;
            #pragma unroll
            for (int e = 0; e < 4; e++)
                AsS[base + e * 20] = vv[e];
        }
    };

    // ---- prologue: B0,B1 in flight; A0 staged; publish tile 0 ----
    {
        float4 ar[8];
        issueB(0, 0); CP_COMMIT();
        issueB(TBK, 1); CP_COMMIT();
        ldA(0, ar);
        stA(0, ar);
        CP_WAIT1();          // B(0) done; B(1) still flying
        __syncthreads();
    }

    for (int it = 0; it < nt; it++) {
        float4 ar[8];
        const bool preA = (it + 1 < nt);
        if (it + 2 < nt) issueB((it + 2) * TBK, (it + 2) % 3);
        CP_COMMIT();                      // exactly one group per iter (may be empty)
        if (preA) ldA((it + 1) * TBK, ar);

        const float* AsS = gsm + (it & 1) * A2_STAGE;
        const float* BsS = Bbase + (it % 3) * B_STAGE;

        #pragma unroll
        for (int kk = 0; kk < 4; kk++) {
            const int k0 = kk * 8;
            uint32_t af[4][4];
            const float4* Ablk = reinterpret_cast<const float4*>(AsS)
                                 + ((kk * 2 + warpM) * 32 + lane) * 5;
            #pragma unroll
            for (int mi = 0; mi < 4; mi++) {
                float4 fv = Ablk[mi];
                af[mi][0] = __float_as_uint(fv.x);
                af[mi][1] = __float_as_uint(fv.y);
                af[mi][2] = __float_as_uint(fv.z);
                af[mi][3] = __float_as_uint(fv.w);
            }
            uint32_t bf[8][2];
            #pragma unroll
            for (int ni = 0; ni < 8; ni++) {
                int n = nBase + ni * 8 + g;
                bf[ni][0] = __float_as_uint(BsS[(k0 + tg) * 136 + n]);
                bf[ni][1] = __float_as_uint(BsS[(k0 + tg + 4) * 136 + n]);
            }
            #pragma unroll
            for (int mi = 0; mi < 4; mi++)
                #pragma unroll
                for (int ni = 0; ni < 8; ni++)
                    mma_tf32(acc[mi][ni][0], acc[mi][ni][1], acc[mi][ni][2], acc[mi][ni][3],
                             af[mi][0], af[mi][1], af[mi][2], af[mi][3],
                             bf[ni][0], bf[ni][1]);
        }

        if (preA) stA((it + 1) & 1, ar);  // writes stage whose readers were fenced at end of it-1
        CP_WAIT1();                       // all groups except newest done -> B(it+1) landed
        __syncthreads();                  // publish tile it+1; fence reads of tile it
    }

    // ---- epilogue ----
    #pragma unroll
    for (int mi = 0; mi < 4; mi++) {
        #pragma unroll
        for (int ri = 0; ri < 2; ri++) {
            int m = (int)rowBlock + mBase + mi * 16 + g + ri * 8;
            #pragma unroll
            for (int ni = 0; ni < 8; ni++) {
                int n = colBlock + nBase + ni * 8 + tg * 2;
                float v0 = acc[mi][ni][ri * 2 + 0];
                float v1 = acc[mi][ni][ri * 2 + 1];
                if (EPI == EPI_QKV) {
                    // store rna-rounded so flash operands are exact tf32
                    int b = m >> 10, s = m & 1023;
                    int h = n >> 6, dk = n & 63;
                    float2 o;
                    o.x = rna_tf32f(v0 * scale);
                    o.y = rna_tf32f(v1 * scale);
                    *(float2*)&C[(((((long)b * HH + h) << 10) + s) << 6) + dk] = o;
                } else if (EPI == EPI_PLAIN) {
                    float2 o; o.x = v0; o.y = v1;
                    *(float2*)&C[(long)m * DD + n] = o;
                } else if (EPI == EPI_BIAS) {
                    float2 o; o.x = v0 + bias[n]; o.y = v1 + bias[n + 1];
                    *(float2*)&C[(long)m * DD + n] = o;
                } else {  // EPI_BIASGELU -> hid (rounded: consumed only by lin2)
                    float2 o;
                    o.x = rna_tf32f(gelu_tanh_f(v0 + bias[n]));
                    o.y = rna_tf32f(gelu_tanh_f(v1 + bias[n + 1]));
                    *(float2*)&C[(long)m * DD + n] = o;
                }
            }
        }
    }
}

template <int EPI>
__global__ __launch_bounds__(128, 2) void gemm_kernel(
    const float* __restrict__ A, const float* __restrict__ Bw,
    const float* __restrict__ bias, float* __restrict__ C, float scale)
{
    gemm_body<EPI>(A, Bw, bias, C, scale);
}

// fused QKV: blockIdx.z selects (input, weight, output, scale)
__global__ __launch_bounds__(128, 2) void gemm_qkv_kernel(
    const float* __restrict__ Q, const float* __restrict__ K,
    const float* __restrict__ V, const float* __restrict__ Wr,
    float invT)
{
    const int z = blockIdx.z;
    const float* A = (z == 0) ? Q : (z == 1) ? K : V;
    float* C = (z == 0) ? g_Qh : (z == 1) ? g_Kh : g_Vh;
    gemm_body<EPI_QKV>(A, Wr + (long)z * WSZ, nullptr, C,
                       (z == 0) ? invT : 1.0f);
}

// ================= Tensor-core flash attention ============================
// Br=64 (4 warps x m16), Bc=64; double-buffered K/V/mask via cp.async with
// prefetch-at-top / barrier-at-end ordering.
#define FL_STAGE 8976
#define FL_P (2*FL_STAGE)                        // 17952
#define FLASH_SMEM_BYTES ((FL_P + 4*1088) * 4)   // 89216

__global__ __launch_bounds__(128) void flash_tc_kernel(
    const unsigned char* __restrict__ mask, float* __restrict__ ctx)
{
    extern __shared__ float fsm[];

    const int t = threadIdx.x;
    const int lane = t & 31, warp = t >> 5;
    const int g = lane >> 2, tg = lane & 3;
    const int qt = blockIdx.x;
    const int h = blockIdx.y;
    const int b = blockIdx.z;
    const long base = ((long)(b * HH + h)) << 16;
    const int q0 = qt * 64;
    const int rowg = warp * 16 + g;
    const int qg0 = q0 + rowg;
    const int qg1 = qg0 + 8;
    float* Pw = fsm + FL_P + warp * (16 * 68);

    // ---- Q fragments via stage-0 Ks area (overwritten later) ----
    {
        float* Ks0 = fsm;
        #pragma unroll
        for (int i = 0; i < 8; i++) {
            int idx = t + 128 * i;
            int r = idx >> 4, c = (idx & 15) << 2;
            *(float4*)&Ks0[r * 68 + c] = *(const float4*)&g_Qh[base + (long)(q0 + r) * 64 + c];
        }
    }
    __syncthreads();
    uint32_t qf[8][4];
    {
        float* Ks0 = fsm;
        #pragma unroll
        for (int kk = 0; kk < 8; kk++) {
            int k0 = kk * 8;
            qf[kk][0] = __float_as_uint(Ks0[rowg * 68 + k0 + tg]);
            qf[kk][1] = __float_as_uint(Ks0[(rowg + 8) * 68 + k0 + tg]);
            qf[kk][2] = __float_as_uint(Ks0[rowg * 68 + k0 + tg + 4]);
            qf[kk][3] = __float_as_uint(Ks0[(rowg + 8) * 68 + k0 + tg + 4]);
        }
    }
    __syncthreads();

    auto prefetch = [&](int kb, int st) {
        float* S = fsm + st * FL_STAGE;
        uint32_t Ksu = smem_u32(S);
        uint32_t Vsu = smem_u32(S + 4352);
        #pragma unroll
        for (int i = 0; i < 8; i++) {
            int idx = t + 128 * i;
            int r = idx >> 4, c = (idx & 15) << 2;
            CP_ASYNC16(Ksu + (uint32_t)(r * 68 + c) * 4, &g_Kh[base + (long)(kb + r) * 64 + c]);
            CP_ASYNC16(Vsu + (uint32_t)(r * 72 + c) * 4, &g_Vh[base + (long)(kb + r) * 64 + c]);
        }
        if (t < 4) {
            uint32_t Mu = smem_u32(S + 8960);
            CP_ASYNC16(Mu + t * 16, mask + (long)b * SS + kb + t * 16);
        }
    };

    float o[8][4];
    #pragma unroll
    for (int i = 0; i < 8; i++)
        #pragma unroll
        for (int j = 0; j < 4; j++) o[i][j] = 0.0f;
    float m0 = -1e30f, m1 = -1e30f, l0 = 0.0f, l1 = 0.0f;

    const int ntiles = qt + 1;

    // prologue: tile 0 -> stage 0
    prefetch(0, 0);
    CP_COMMIT();
    CP_WAIT0();
    __syncthreads();

    for (int kt = 0; kt < ntiles; kt++) {
        const int kb = kt * 64;
        const int st = kt & 1;
        const bool pre = (kt + 1 < ntiles);
        if (pre) {
            prefetch(kb + 64, st ^ 1);   // safe: readers fenced by prior barrier
            CP_COMMIT();
        }

        const float* Ks = fsm + st * FL_STAGE;
        const float* Vs = Ks + 4352;
        const unsigned char* Msk = (const unsigned char*)(Ks + 8960);

        // ---- S = Q . K^T ----
        float s[8][4];
        #pragma unroll
        for (int i = 0; i < 8; i++)
            #pragma unroll
            for (int j = 0; j < 4; j++) s[i][j] = 0.0f;
        #pragma unroll
        for (int kk = 0; kk < 8; kk++) {
            int k0 = kk * 8;
            #pragma unroll
            for (int ni = 0; ni < 8; ni++) {
                uint32_t b0 = __float_as_uint(Ks[(ni * 8 + g) * 68 + k0 + tg]);
                uint32_t b1 = __float_as_uint(Ks[(ni * 8 + g) * 68 + k0 + tg + 4]);
                mma_tf32(s[ni][0], s[ni][1], s[ni][2], s[ni][3],
                         qf[kk][0], qf[kk][1], qf[kk][2], qf[kk][3], b0, b1);
            }
        }

        // ---- mask + row max ----
        float tmax0 = -1e30f, tmax1 = -1e30f;
        if (kb + 64 > q0) {
            // diagonal tile: causal + pad
            #pragma unroll
            for (int ni = 0; ni < 8; ni++) {
                int cl = ni * 8 + 2 * tg;
                int c0g = kb + cl, c1g = c0g + 1;
                bool pm0 = Msk[cl] != 0, pm1 = Msk[cl + 1] != 0;
                if (c0g > qg0 || pm0) s[ni][0] = -1e30f;
                if (c1g > qg0 || pm1) s[ni][1] = -1e30f;
                if (c0g > qg1 || pm0) s[ni][2] = -1e30f;
                if (c1g > qg1 || pm1) s[ni][3] = -1e30f;
                tmax0 = fmaxf(tmax0, fmaxf(s[ni][0], s[ni][1]));
                tmax1 = fmaxf(tmax1, fmaxf(s[ni][2], s[ni][3]));
            }
        } else {
            // strictly-below-diagonal: pad mask only
            #pragma unroll
            for (int ni = 0; ni < 8; ni++) {
                int cl = ni * 8 + 2 * tg;
                bool pm0 = Msk[cl] != 0, pm1 = Msk[cl + 1] != 0;
                if (pm0) { s[ni][0] = -1e30f; s[ni][2] = -1e30f; }
                if (pm1) { s[ni][1] = -1e30f; s[ni][3] = -1e30f; }
                tmax0 = fmaxf(tmax0, fmaxf(s[ni][0], s[ni][1]));
                tmax1 = fmaxf(tmax1, fmaxf(s[ni][2], s[ni][3]));
            }
        }
        #pragma unroll
        for (int off = 1; off <= 2; off <<= 1) {
            tmax0 = fmaxf(tmax0, __shfl_xor_sync(0xffffffffu, tmax0, off));
            tmax1 = fmaxf(tmax1, __shfl_xor_sync(0xffffffffu, tmax1, off));
        }

        float mnew0 = fmaxf(m0, tmax0), mnew1 = fmaxf(m1, tmax1);
        float corr0 = __expf(m0 - mnew0), corr1 = __expf(m1 - mnew1);

        // P = rna(exp(S-m)) (rounded values feed BOTH l and P.V)
        float ls0 = 0.0f, ls1 = 0.0f;
        #pragma unroll
        for (int ni = 0; ni < 8; ni++) {
            float p00 = rna_tf32f(__expf(s[ni][0] - mnew0));
            float p01 = rna_tf32f(__expf(s[ni][1] - mnew0));
            float p10 = rna_tf32f(__expf(s[ni][2] - mnew1));
            float p11 = rna_tf32f(__expf(s[ni][3] - mnew1));
            ls0 += p00 + p01;
            ls1 += p10 + p11;
            int cl = ni * 8 + 2 * tg;
            *(float2*)&Pw[g * 68 + cl] = make_float2(p00, p01);
            *(float2*)&Pw[(g + 8) * 68 + cl] = make_float2(p10, p11);
        }
        #pragma unroll
        for (int off = 1; off <= 2; off <<= 1) {
            ls0 += __shfl_xor_sync(0xffffffffu, ls0, off);
            ls1 += __shfl_xor_sync(0xffffffffu, ls1, off);
        }
        l0 = l0 * corr0 + ls0;
        l1 = l1 * corr1 + ls1;
        m0 = mnew0; m1 = mnew1;

        #pragma unroll
        for (int ni = 0; ni < 8; ni++) {
            o[ni][0] *= corr0; o[ni][1] *= corr0;
            o[ni][2] *= corr1; o[ni][3] *= corr1;
        }
        __syncwarp();   // Pw visible within warp

        // ---- O += P . V ----
        #pragma unroll
        for (int kk = 0; kk < 8; kk++) {
            int k0 = kk * 8;
            uint32_t a0 = __float_as_uint(Pw[g * 68 + k0 + tg]);
            uint32_t a1 = __float_as_uint(Pw[(g + 8) * 68 + k0 + tg]);
            uint32_t a2 = __float_as_uint(Pw[g * 68 + k0 + tg + 4]);
            uint32_t a3 = __float_as_uint(Pw[(g + 8) * 68 + k0 + tg + 4]);
            #pragma unroll
            for (int ni = 0; ni < 8; ni++) {
                uint32_t b0 = __float_as_uint(Vs[(k0 + tg) * 72 + ni * 8 + g]);
                uint32_t b1 = __float_as_uint(Vs[(k0 + tg + 4) * 72 + ni * 8 + g]);
                mma_tf32(o[ni][0], o[ni][1], o[ni][2], o[ni][3], a0, a1, a2, a3, b0, b1);
            }
        }

        if (pre) CP_WAIT0();   // next tile landed (overlapped with compute)
        __syncthreads();       // close iter: publish next tile, fence reads of st
    }

    const float inv0 = 1.0f / l0, inv1 = 1.0f / l1;
    float* dst0 = &ctx[((long)(b * SS + qg0)) * DD + h * DKK];
    float* dst1 = &ctx[((long)(b * SS + qg1)) * DD + h * DKK];
    #pragma unroll
    for (int ni = 0; ni < 8; ni++) {
        int cl = ni * 8 + 2 * tg;
        *(float2*)&dst0[cl] = make_float2(o[ni][0] * inv0, o[ni][1] * inv0);
        *(float2*)&dst1[cl] = make_float2(o[ni][2] * inv1, o[ni][3] * inv1);
    }
}

// ---------------- residual + LayerNorm (float4, 128 thr/row) --------------
__global__ __launch_bounds__(128) void ln_kernel(
    const float* __restrict__ X, const float* __restrict__ R,
    const float* __restrict__ g, const float* __restrict__ bta,
    float* __restrict__ out)
{
    const int row = blockIdx.x;
    const int t = threadIdx.x;
    const long rb = (long)row * DD;
    float4 a = *(const float4*)&X[rb + t * 4];
    float4 r = *(const float4*)&R[rb + t * 4];
    float4 xv = make_float4(a.x + r.x, a.y + r.y, a.z + r.z, a.w + r.w);

    __shared__ float red[4], red2[4];

    float s = xv.x + xv.y + xv.z + xv.w;
    #pragma unroll
    for (int o = 16; o; o >>= 1) s += __shfl_xor_sync(0xffffffffu, s, o);
    if ((t & 31) == 0) red[t >> 5] = s;
    __syncthreads();
    const float mu = (red[0] + red[1] + red[2] + red[3]) * (1.0f / DD);

    float4 d = make_float4(xv.x - mu, xv.y - mu, xv.z - mu, xv.w - mu);
    float s2 = d.x * d.x + d.y * d.y + d.z * d.z + d.w * d.w;
    #pragma unroll
    for (int o = 16; o; o >>= 1) s2 += __shfl_xor_sync(0xffffffffu, s2, o);
    if ((t & 31) == 0) red2[t >> 5] = s2;
    __syncthreads();
    const float rstd = rsqrtf((red2[0] + red2[1] + red2[2] + red2[3]) * (1.0f / DD) + 1e-5f);

    float4 gg = *(const float4*)&g[t * 4];
    float4 bb = *(const float4*)&bta[t * 4];
    float4 o4;
    o4.x = d.x * rstd * gg.x + bb.x;
    o4.y = d.y * rstd * gg.y + bb.y;
    o4.z = d.z * rstd * gg.z + bb.z;
    o4.w = d.w * rstd * gg.w + bb.w;
    *(float4*)&out[rb + t * 4] = o4;
}

// ---------------- launch ----------------
extern "C" void kernel_launch(void* const* d_in, const int* in_sizes, int n_in,
                              void* d_out, int out_size)
{
    const float* Q      = (const float*)d_in[0];
    const float* K      = (const float*)d_in[1];
    const float* V      = (const float*)d_in[2];
    const unsigned char* mask = (const unsigned char*)d_in[3];
    const float* W_q    = (const float*)d_in[4];
    const float* W_k    = (const float*)d_in[5];
    const float* W_v    = (const float*)d_in[6];
    const float* W_o    = (const float*)d_in[7];
    const float* lin1_w = (const float*)d_in[8];
    const float* lin1_b = (const float*)d_in[9];
    const float* lin2_w = (const float*)d_in[10];
    const float* lin2_b = (const float*)d_in[11];
    const float* ln_g   = (const float*)d_in[12];
    const float* ln_b   = (const float*)d_in[13];
    float* out = (float*)d_out;

    float *ctx, *att, *out1, *hid, *ffn, *Wr;
    cudaGetSymbolAddress((void**)&ctx, g_ctx);
    cudaGetSymbolAddress((void**)&att, g_att);
    cudaGetSymbolAddress((void**)&out1, g_out1);
    cudaGetSymbolAddress((void**)&hid, g_hid);
    cudaGetSymbolAddress((void**)&ffn, g_ffn);
    cudaGetSymbolAddress((void**)&Wr,  g_Wr);

    cudaFuncSetAttribute(gemm_qkv_kernel,
                         cudaFuncAttributeMaxDynamicSharedMemorySize, GEMM_SMEM_BYTES);
    cudaFuncSetAttribute(gemm_kernel<EPI_PLAIN>,
                         cudaFuncAttributeMaxDynamicSharedMemorySize, GEMM_SMEM_BYTES);
    cudaFuncSetAttribute(gemm_kernel<EPI_BIAS>,
                         cudaFuncAttributeMaxDynamicSharedMemorySize, GEMM_SMEM_BYTES);
    cudaFuncSetAttribute(gemm_kernel<EPI_BIASGELU>,
                         cudaFuncAttributeMaxDynamicSharedMemorySize, GEMM_SMEM_BYTES);
    cudaFuncSetAttribute(flash_tc_kernel,
                         cudaFuncAttributeMaxDynamicSharedMemorySize, FLASH_SMEM_BYTES);

    // 0) pre-round all weights (rna -> kills tf32 truncation bias)
    wround_kernel<<<dim3(256, 6), 256>>>(W_q, W_k, W_v, W_o, lin1_w, lin2_w, Wr);

    dim3 ggrid(DD / 128, MROWS / 128);         // (4, 128)
    const float invT = 1.0f / (8.0f + 1e-6f);  // 1/(sqrt(DK)+eps), folded into Q proj

    // 1) fused QKV projections (rounded head-layout outputs)
    gemm_qkv_kernel<<<dim3(4, 128, 3), 128, GEMM_SMEM_BYTES>>>(Q, K, V, Wr, invT);

    // 2) attention
    flash_tc_kernel<<<dim3(SS / 64, HH, BB), 128, FLASH_SMEM_BYTES>>>(mask, ctx);

    // 3) output projection + residual LN
    gemm_kernel<EPI_PLAIN><<<ggrid, 128, GEMM_SMEM_BYTES>>>(ctx, Wr + 3L * WSZ, nullptr, att, 1.0f);
    ln_kernel<<<MROWS, 128>>>(att, Q, ln_g, ln_b, out1);

    // 4) FFN
    gemm_kernel<EPI_BIASGELU><<<ggrid, 128, GEMM_SMEM_BYTES>>>(out1, Wr + 4L * WSZ, lin1_b, hid, 1.0f);
    gemm_kernel<EPI_BIAS><<<ggrid, 128, GEMM_SMEM_BYTES>>>(hid, Wr + 5L * WSZ, lin2_b, ffn, 1.0f);
    ln_kernel<<<MROWS, 128>>>(ffn, out1, ln_g, ln_b, out);
}